// round 13
// baseline (speedup 1.0000x reference)
#include <cuda_runtime.h>
#include <math.h>

#define MM 2000
#define NB 4096
#define CAND 4096
#define EDGE_MAX 4096
#define T_STATIC 0.9994f
#define TB 64
#define NT ((MM + TB - 1) / TB)        // 32 tiles per dim
#define NTILES (NT * (NT + 1) / 2)     // 528 upper-triangle tiles
#define GRID 296                       // 2 CTAs/SM x 148 SMs — fully co-resident

// ---------------- device scratch (zero-initialized at module load) ----------------
__device__ int                g_candCount;
__device__ int                g_cnt;
__device__ int                g_nValid;
__device__ int                g_edgeCount;
__device__ unsigned           g_done1, g_done2;
__device__ unsigned long long g_cand[CAND];
__device__ float4             g_boxes[MM];
__device__ int                g_keep0[MM];
__device__ unsigned int       g_edges[EDGE_MAX];
__device__ volatile unsigned  g_gen;
__device__ unsigned           g_arrive;

// ---------------- grid barrier (all GRID blocks resident by construction) --------
__device__ __forceinline__ void grid_barrier() {
    __syncthreads();
    if (threadIdx.x == 0) {
        __threadfence();
        unsigned gen = g_gen;
        if (atomicAdd(&g_arrive, 1u) == (unsigned)gridDim.x - 1u) {
            atomicExch(&g_arrive, 0u);
            __threadfence();
            g_gen = gen + 1u;
        } else {
            while (g_gen == gen) __nanosleep(64);
        }
        __threadfence();
    }
    __syncthreads();
}

// ---------------- one launch: stream | validate | rank | pairs | finalize --------
__global__ void __launch_bounds__(1024, 2) k_all2(
    const float4* __restrict__ s4, int n4,
    const float2* __restrict__ score, int n,
    const float4* __restrict__ anchors,
    const float4* __restrict__ deltas,
    float* __restrict__ out)
{
    __shared__ union {
        unsigned long long keys[CAND];                                  // 32 KB (rank)
        unsigned hist[NB];                                              // 16 KB (fallback)
        struct { unsigned se[EDGE_MAX]; unsigned se2[EDGE_MAX];
                 unsigned char dead[MM]; } fin;                         // 34.4 KB
    } sh;
    __shared__ int s_rank[32];
    __shared__ float4 bjs[TB];
    __shared__ float  ajs[TB];
    __shared__ int    kjs[TB];
    int t = threadIdx.x;

    // ========== Phase 1: streaming speculative compact (32 MB read) ==========
    {
        int nthr = gridDim.x * blockDim.x;
        int tid  = blockIdx.x * blockDim.x + t;
        for (int i = tid; i < n4; i += 4 * nthr) {
            int i1 = i + nthr, i2 = i + 2 * nthr, i3 = i + 3 * nthr;
            bool b1 = i1 < n4, b2 = i2 < n4, b3 = i3 < n4;
            float4 a0 = s4[i];
            float4 a1, a2, a3;
            if (b1) a1 = s4[i1];
            if (b2) a2 = s4[i2];
            if (b3) a3 = s4[i3];
            #define EMIT(v, idx)                                                        \
                if ((v) > T_STATIC) {                                                   \
                    int pos = atomicAdd(&g_candCount, 1);                               \
                    if (pos < CAND)                                                     \
                        g_cand[pos] = ((unsigned long long)__float_as_uint(v) << 32) |  \
                                      (unsigned long long)(0xFFFFFFFFu - (idx));        \
                }
            EMIT(a0.y, 2u * (unsigned)i)
            EMIT(a0.w, 2u * (unsigned)i + 1u)
            if (b1) { EMIT(a1.y, 2u * (unsigned)i1) EMIT(a1.w, 2u * (unsigned)i1 + 1u) }
            if (b2) { EMIT(a2.y, 2u * (unsigned)i2) EMIT(a2.w, 2u * (unsigned)i2 + 1u) }
            if (b3) { EMIT(a3.y, 2u * (unsigned)i3) EMIT(a3.w, 2u * (unsigned)i3 + 1u) }
            #undef EMIT
        }
    }

    // ---- validation by the LAST block to finish streaming (no barrier needed:
    //      everyone else proceeds to grid_barrier and waits; the validator's
    //      g_cnt/g_nValid writes are ordered by the barrier's fences) ----
    {
        __shared__ int s_last;
        __syncthreads();
        if (t == 0) {
            __threadfence();
            unsigned d = atomicAdd(&g_done1, 1u);
            s_last = (d == gridDim.x - 1) ? 1 : 0;
        }
        __syncthreads();
        if (s_last) {
            __shared__ int s_fb;
            if (t == 0) {
                g_done1 = 0;
                int c = g_candCount;
                s_fb = (c < MM || c > CAND);
                if (!s_fb) { g_cnt = c; g_nValid = MM; g_edgeCount = 0; }
            }
            __syncthreads();
            if (s_fb) {
                // pathological fallback: exact histogram selection by this block
                __shared__ unsigned s_cut;
                __shared__ int s_cnt2;
                for (int i = t; i < NB; i += 1024) sh.hist[i] = 0u;
                __syncthreads();
                for (int i = t; i < n; i += 1024) {
                    float v = score[i].y;
                    if (v > 0.5f) {
                        unsigned u = __float_as_uint(v);
                        unsigned b = (u - 0x3F000000u) >> 11;
                        if (b > NB - 1u) b = NB - 1u;
                        atomicAdd(&sh.hist[b], 1u);
                    }
                }
                __syncthreads();
                if (t == 0) {
                    unsigned run = 0; unsigned cut = 0;
                    for (int b = NB - 1; b >= 0; b--) {
                        run += sh.hist[b];
                        if (run >= (unsigned)MM) { cut = (unsigned)b; break; }
                    }
                    s_cut = cut;
                    s_cnt2 = 0;
                }
                __syncthreads();
                unsigned cut = s_cut;
                for (int i = t; i < n; i += 1024) {
                    float v = score[i].y;
                    if (v > 0.5f) {
                        unsigned u = __float_as_uint(v);
                        unsigned b = (u - 0x3F000000u) >> 11;
                        if (b > NB - 1u) b = NB - 1u;
                        if (b >= cut) {
                            int pos = atomicAdd(&s_cnt2, 1);
                            if (pos < CAND)
                                g_cand[pos] = ((unsigned long long)u << 32) |
                                              (unsigned long long)(0xFFFFFFFFu - (unsigned)i);
                        }
                    }
                }
                __syncthreads();
                if (t == 0) {
                    int c2 = s_cnt2; if (c2 > CAND) c2 = CAND;
                    g_cnt = c2;
                    g_nValid = (c2 < MM) ? c2 : MM;
                    g_edgeCount = 0;
                }
            }
        }
    }

    grid_barrier();   // g_cand/g_cnt/g_nValid visible chip-wide

    int cnt = g_cnt;
    int nV  = g_nValid;

    // ========== Phase A: sliced rank — every block ranks cpb candidates ==========
    {
        int cpb = (cnt + (int)gridDim.x - 1) / (int)gridDim.x;
        int cBase = blockIdx.x * cpb;
        if (cpb > 0 && cBase < cnt) {
            int wpc = 32 / cpb;
            int cntR = (cnt + 127) & ~127;
            for (int i = t; i < cntR; i += 1024) sh.keys[i] = (i < cnt) ? g_cand[i] : 0ULL;
            if (t < 32) s_rank[t] = 0;
            __syncthreads();
            int wid = t >> 5, lane = t & 31;
            int c = wid / wpc;
            int s = wid - c * wpc;
            int gc = cBase + c;
            if (c < cpb && gc < cnt) {
                unsigned long long my = sh.keys[gc];
                int sliceLen = (((cntR + wpc - 1) / wpc) + 127) & ~127;
                int b0 = s * sliceLen;
                int b1 = min(b0 + sliceLen, cntR);
                int g = 0;
                for (int base = b0; base < b1; base += 64) {
                    unsigned long long k0 = sh.keys[base      + lane];
                    unsigned long long k1 = sh.keys[base + 32 + lane];
                    g += __popc(__ballot_sync(0xffffffffu, k0 > my));
                    g += __popc(__ballot_sync(0xffffffffu, k1 > my));
                }
                if (lane == 0 && g) atomicAdd(&s_rank[c], g);
            }
            __syncthreads();
            if (t < cpb && cBase + t < cnt) {
                int g = s_rank[t];
                if (g < MM) {
                    unsigned long long my = sh.keys[cBase + t];
                    unsigned idx = 0xFFFFFFFFu - (unsigned)(my & 0xFFFFFFFFull);
                    float4 a = __ldg(anchors + idx);
                    float4 d = __ldg(deltas + idx);
                    float w  = a.z - a.x;
                    float h  = a.w - a.y;
                    float cx = a.x + 0.5f * w;
                    float cy = a.y + 0.5f * h;
                    float ncx = cx + d.x * w;
                    float ncy = cy + d.y * h;
                    float nw  = w * expf(d.z);
                    float nh  = h * expf(d.w);
                    float x1 = ncx - 0.5f * nw, y1 = ncy - 0.5f * nh;
                    float x2 = ncx + 0.5f * nw, y2 = ncy + 0.5f * nh;
                    x1 = fminf(fmaxf(x1, 0.f), 1024.f);
                    y1 = fminf(fmaxf(y1, 0.f), 1024.f);
                    x2 = fminf(fmaxf(x2, 0.f), 1024.f);
                    y2 = fminf(fmaxf(y2, 0.f), 1024.f);
                    bool big = ((x2 - x1) >= 1.0f) && ((y2 - y1) >= 1.0f);
                    g_boxes[g] = make_float4(x1, y1, x2, y2);
                    g_keep0[g] = big ? 1 : 0;
                }
            }
        }
    }

    grid_barrier();   // all boxes/keep0 visible chip-wide

    // ========== Phase B: pairs — 64x64 tiles strided over the grid ==========
    for (int tile = blockIdx.x; tile < NTILES; tile += gridDim.x) {
        int bx = 0, rem = tile;
        while (rem >= NT - bx) { rem -= NT - bx; bx++; }
        int by = bx + rem;

        __syncthreads();
        if (t < TB) {
            int j = by * TB + t;
            if (j < nV) {
                float4 b = g_boxes[j];
                bjs[t] = b; ajs[t] = (b.z - b.x) * (b.w - b.y); kjs[t] = g_keep0[j];
            } else kjs[t] = 0;
        }
        __syncthreads();

        int li = t >> 4;
        int i  = bx * TB + li;
        if (i < nV && g_keep0[i]) {
            float4 A = g_boxes[i];
            float ai = (A.z - A.x) * (A.w - A.y);
            int ljBase = (t & 15) * 4;
            int jBase  = by * TB + ljBase;
            #pragma unroll
            for (int u = 0; u < 4; u++) {
                int lj = ljBase + u;
                int j  = jBase + u;
                if (j > i && j < nV && kjs[lj]) {
                    float4 B = bjs[lj];
                    float ltx = fmaxf(A.x, B.x), lty = fmaxf(A.y, B.y);
                    float rbx = fminf(A.z, B.z), rby = fminf(A.w, B.w);
                    float iw = fmaxf(rbx - ltx, 0.f), ih = fmaxf(rby - lty, 0.f);
                    float inter = iw * ih;
                    float iou = inter / (ai + ajs[lj] - inter + 1e-9f);
                    if (iou > 0.7f) {
                        int pos = atomicAdd(&g_edgeCount, 1);
                        if (pos < EDGE_MAX) g_edges[pos] = ((unsigned)i << 16) | (unsigned)j;
                    }
                }
            }
        }
    }

    // ========== last-finishing block: finalize ==========
    __shared__ int s_last2;
    __syncthreads();
    if (t == 0) {
        __threadfence();
        unsigned d = atomicAdd(&g_done2, 1u);
        s_last2 = (d == gridDim.x - 1) ? 1 : 0;
    }
    __syncthreads();
    if (!s_last2) return;

    for (int m = t; m < MM; m += 1024) sh.fin.dead[m] = (m < nV && g_keep0[m]) ? 0 : 1;
    int ec = g_edgeCount; if (ec > EDGE_MAX) ec = EDGE_MAX;
    for (int i = t; i < ec; i += 1024) sh.fin.se[i] = g_edges[i];
    __syncthreads();

    // parallel counting-rank sort of edges (distinct (i<<16|j) keys)
    for (int e = t; e < ec; e += 1024) {
        unsigned key = sh.fin.se[e];
        int r = 0;
        for (int f = 0; f < ec; f++) r += (sh.fin.se[f] < key) ? 1 : 0;
        sh.fin.se2[r] = key;
    }
    __syncthreads();

    if (t == 0) {
        for (int e = 0; e < ec; e++) {
            unsigned u = sh.fin.se2[e];
            int i = (int)(u >> 16), j = (int)(u & 0xFFFFu);
            if (!sh.fin.dead[i]) sh.fin.dead[j] = 1;
        }
    }
    __syncthreads();

    for (int m = t; m < MM; m += 1024) {
        bool keep = (sh.fin.dead[m] == 0);
        float4 b = g_boxes[m];
        out[m * 4 + 0] = keep ? b.x : 0.f;
        out[m * 4 + 1] = keep ? b.y : 0.f;
        out[m * 4 + 2] = keep ? b.z : 0.f;
        out[m * 4 + 3] = keep ? b.w : 0.f;
        out[MM * 4 + m] = keep ? 1.f : 0.f;
    }
    __syncthreads();
    if (t == 0) {   // reset for next replay
        g_candCount = 0;
        g_edgeCount = 0;
        g_done2 = 0;
    }
}

// ---------------- launch ----------------
extern "C" void kernel_launch(void* const* d_in, const int* in_sizes, int n_in,
                              void* d_out, int out_size) {
    int si = 0;
    for (int i = 1; i < n_in; i++) if (in_sizes[i] < in_sizes[si]) si = i;
    int others[2], o = 0;
    for (int i = 0; i < n_in && o < 2; i++) if (i != si) others[o++] = i;

    const float4* anchors = (const float4*)d_in[others[0]];
    const float2* score   = (const float2*)d_in[si];
    const float4* deltas  = (const float4*)d_in[others[1]];
    int n  = in_sizes[si] / 2;
    int n4 = in_sizes[si] / 4;

    k_all2<<<GRID, 1024>>>((const float4*)score, n4, score, n,
                           anchors, deltas, (float*)d_out);
}

// round 14
// speedup vs baseline: 1.0097x; 1.0097x over previous
#include <cuda_runtime.h>
#include <math.h>

#define MM 2000
#define NB 4096
#define CAND 4096
#define EDGE_MAX 4096
#define T_STATIC 0.9994f
#define TB 64
#define NT ((MM + TB - 1) / TB)        // 32 tiles per dim
#define NTILES (NT * (NT + 1) / 2)     // 528 upper-triangle tiles
#define GRID 296                       // 2 CTAs/SM x 148 SMs — fully co-resident

// ---------------- device scratch (zero-initialized at module load) ----------------
__device__ int                g_candCount;
__device__ int                g_cnt;
__device__ int                g_nValid;
__device__ int                g_edgeCount;
__device__ unsigned           g_done1, g_done2;
__device__ unsigned long long g_cand[CAND];
__device__ float4             g_boxes[MM];
__device__ int                g_keep0[MM];
__device__ unsigned int       g_edges[EDGE_MAX];
__device__ volatile unsigned  g_gen;
__device__ unsigned           g_arrive;

// ---------------- grid barrier (all GRID blocks resident by construction) --------
__device__ __forceinline__ void grid_barrier() {
    __syncthreads();
    if (threadIdx.x == 0) {
        __threadfence();
        unsigned gen = g_gen;
        if (atomicAdd(&g_arrive, 1u) == (unsigned)gridDim.x - 1u) {
            atomicExch(&g_arrive, 0u);
            __threadfence();
            g_gen = gen + 1u;
        } else {
            while (g_gen == gen) __nanosleep(64);
        }
        __threadfence();
    }
    __syncthreads();
}

// ---------------- one launch: stream | validate | rank | pairs | finalize --------
__global__ void __launch_bounds__(1024, 2) k_all2(
    const float4* __restrict__ s4, int n4,
    const float2* __restrict__ score, int n,
    const float4* __restrict__ anchors,
    const float4* __restrict__ deltas,
    float* __restrict__ out)
{
    __shared__ union {
        unsigned long long keys[CAND];                                  // 32 KB (rank)
        unsigned hist[NB];                                              // 16 KB (fallback)
        struct { unsigned se[EDGE_MAX]; unsigned se2[EDGE_MAX];
                 unsigned char dead[MM]; } fin;                         // 34.4 KB
    } sh;
    __shared__ int s_rank[32];
    __shared__ float4 bjs[TB];
    __shared__ float  ajs[TB];
    __shared__ int    kjs[TB];
    int t = threadIdx.x;

    // ========== Phase 1: streaming speculative compact (32 MB read) ==========
    {
        int nthr = gridDim.x * blockDim.x;
        int tid  = blockIdx.x * blockDim.x + t;
        for (int i = tid; i < n4; i += 4 * nthr) {
            int i1 = i + nthr, i2 = i + 2 * nthr, i3 = i + 3 * nthr;
            bool b1 = i1 < n4, b2 = i2 < n4, b3 = i3 < n4;
            float4 a0 = s4[i];
            float4 a1, a2, a3;
            if (b1) a1 = s4[i1];
            if (b2) a2 = s4[i2];
            if (b3) a3 = s4[i3];
            #define EMIT(v, idx)                                                        \
                if ((v) > T_STATIC) {                                                   \
                    int pos = atomicAdd(&g_candCount, 1);                               \
                    if (pos < CAND)                                                     \
                        g_cand[pos] = ((unsigned long long)__float_as_uint(v) << 32) |  \
                                      (unsigned long long)(0xFFFFFFFFu - (idx));        \
                }
            EMIT(a0.y, 2u * (unsigned)i)
            EMIT(a0.w, 2u * (unsigned)i + 1u)
            if (b1) { EMIT(a1.y, 2u * (unsigned)i1) EMIT(a1.w, 2u * (unsigned)i1 + 1u) }
            if (b2) { EMIT(a2.y, 2u * (unsigned)i2) EMIT(a2.w, 2u * (unsigned)i2 + 1u) }
            if (b3) { EMIT(a3.y, 2u * (unsigned)i3) EMIT(a3.w, 2u * (unsigned)i3 + 1u) }
            #undef EMIT
        }
    }

    // ---- validation by the LAST block to finish streaming (no barrier needed:
    //      everyone else proceeds to grid_barrier and waits; the validator's
    //      g_cnt/g_nValid writes are ordered by the barrier's fences) ----
    {
        __shared__ int s_last;
        __syncthreads();
        if (t == 0) {
            __threadfence();
            unsigned d = atomicAdd(&g_done1, 1u);
            s_last = (d == gridDim.x - 1) ? 1 : 0;
        }
        __syncthreads();
        if (s_last) {
            __shared__ int s_fb;
            if (t == 0) {
                g_done1 = 0;
                int c = g_candCount;
                s_fb = (c < MM || c > CAND);
                if (!s_fb) { g_cnt = c; g_nValid = MM; g_edgeCount = 0; }
            }
            __syncthreads();
            if (s_fb) {
                // pathological fallback: exact histogram selection by this block
                __shared__ unsigned s_cut;
                __shared__ int s_cnt2;
                for (int i = t; i < NB; i += 1024) sh.hist[i] = 0u;
                __syncthreads();
                for (int i = t; i < n; i += 1024) {
                    float v = score[i].y;
                    if (v > 0.5f) {
                        unsigned u = __float_as_uint(v);
                        unsigned b = (u - 0x3F000000u) >> 11;
                        if (b > NB - 1u) b = NB - 1u;
                        atomicAdd(&sh.hist[b], 1u);
                    }
                }
                __syncthreads();
                if (t == 0) {
                    unsigned run = 0; unsigned cut = 0;
                    for (int b = NB - 1; b >= 0; b--) {
                        run += sh.hist[b];
                        if (run >= (unsigned)MM) { cut = (unsigned)b; break; }
                    }
                    s_cut = cut;
                    s_cnt2 = 0;
                }
                __syncthreads();
                unsigned cut = s_cut;
                for (int i = t; i < n; i += 1024) {
                    float v = score[i].y;
                    if (v > 0.5f) {
                        unsigned u = __float_as_uint(v);
                        unsigned b = (u - 0x3F000000u) >> 11;
                        if (b > NB - 1u) b = NB - 1u;
                        if (b >= cut) {
                            int pos = atomicAdd(&s_cnt2, 1);
                            if (pos < CAND)
                                g_cand[pos] = ((unsigned long long)u << 32) |
                                              (unsigned long long)(0xFFFFFFFFu - (unsigned)i);
                        }
                    }
                }
                __syncthreads();
                if (t == 0) {
                    int c2 = s_cnt2; if (c2 > CAND) c2 = CAND;
                    g_cnt = c2;
                    g_nValid = (c2 < MM) ? c2 : MM;
                    g_edgeCount = 0;
                }
            }
        }
    }

    grid_barrier();   // g_cand/g_cnt/g_nValid visible chip-wide

    int cnt = g_cnt;
    int nV  = g_nValid;

    // ========== Phase A: sliced rank — every block ranks cpb candidates ==========
    {
        int cpb = (cnt + (int)gridDim.x - 1) / (int)gridDim.x;
        int cBase = blockIdx.x * cpb;
        if (cpb > 0 && cBase < cnt) {
            int wpc = 32 / cpb;
            int cntR = (cnt + 127) & ~127;
            for (int i = t; i < cntR; i += 1024) sh.keys[i] = (i < cnt) ? g_cand[i] : 0ULL;
            if (t < 32) s_rank[t] = 0;
            __syncthreads();
            int wid = t >> 5, lane = t & 31;
            int c = wid / wpc;
            int s = wid - c * wpc;
            int gc = cBase + c;
            if (c < cpb && gc < cnt) {
                unsigned long long my = sh.keys[gc];
                int sliceLen = (((cntR + wpc - 1) / wpc) + 127) & ~127;
                int b0 = s * sliceLen;
                int b1 = min(b0 + sliceLen, cntR);
                int g = 0;
                for (int base = b0; base < b1; base += 64) {
                    unsigned long long k0 = sh.keys[base      + lane];
                    unsigned long long k1 = sh.keys[base + 32 + lane];
                    g += __popc(__ballot_sync(0xffffffffu, k0 > my));
                    g += __popc(__ballot_sync(0xffffffffu, k1 > my));
                }
                if (lane == 0 && g) atomicAdd(&s_rank[c], g);
            }
            __syncthreads();
            if (t < cpb && cBase + t < cnt) {
                int g = s_rank[t];
                if (g < MM) {
                    unsigned long long my = sh.keys[cBase + t];
                    unsigned idx = 0xFFFFFFFFu - (unsigned)(my & 0xFFFFFFFFull);
                    float4 a = __ldg(anchors + idx);
                    float4 d = __ldg(deltas + idx);
                    float w  = a.z - a.x;
                    float h  = a.w - a.y;
                    float cx = a.x + 0.5f * w;
                    float cy = a.y + 0.5f * h;
                    float ncx = cx + d.x * w;
                    float ncy = cy + d.y * h;
                    float nw  = w * expf(d.z);
                    float nh  = h * expf(d.w);
                    float x1 = ncx - 0.5f * nw, y1 = ncy - 0.5f * nh;
                    float x2 = ncx + 0.5f * nw, y2 = ncy + 0.5f * nh;
                    x1 = fminf(fmaxf(x1, 0.f), 1024.f);
                    y1 = fminf(fmaxf(y1, 0.f), 1024.f);
                    x2 = fminf(fmaxf(x2, 0.f), 1024.f);
                    y2 = fminf(fmaxf(y2, 0.f), 1024.f);
                    bool big = ((x2 - x1) >= 1.0f) && ((y2 - y1) >= 1.0f);
                    g_boxes[g] = make_float4(x1, y1, x2, y2);
                    g_keep0[g] = big ? 1 : 0;
                }
            }
        }
    }

    grid_barrier();   // all boxes/keep0 visible chip-wide

    // ========== Phase B: pairs — 64x64 tiles strided over the grid ==========
    for (int tile = blockIdx.x; tile < NTILES; tile += gridDim.x) {
        int bx = 0, rem = tile;
        while (rem >= NT - bx) { rem -= NT - bx; bx++; }
        int by = bx + rem;

        __syncthreads();
        if (t < TB) {
            int j = by * TB + t;
            if (j < nV) {
                float4 b = g_boxes[j];
                bjs[t] = b; ajs[t] = (b.z - b.x) * (b.w - b.y); kjs[t] = g_keep0[j];
            } else kjs[t] = 0;
        }
        __syncthreads();

        int li = t >> 4;
        int i  = bx * TB + li;
        if (i < nV && g_keep0[i]) {
            float4 A = g_boxes[i];
            float ai = (A.z - A.x) * (A.w - A.y);
            int ljBase = (t & 15) * 4;
            int jBase  = by * TB + ljBase;
            #pragma unroll
            for (int u = 0; u < 4; u++) {
                int lj = ljBase + u;
                int j  = jBase + u;
                if (j > i && j < nV && kjs[lj]) {
                    float4 B = bjs[lj];
                    float ltx = fmaxf(A.x, B.x), lty = fmaxf(A.y, B.y);
                    float rbx = fminf(A.z, B.z), rby = fminf(A.w, B.w);
                    float iw = fmaxf(rbx - ltx, 0.f), ih = fmaxf(rby - lty, 0.f);
                    float inter = iw * ih;
                    float iou = inter / (ai + ajs[lj] - inter + 1e-9f);
                    if (iou > 0.7f) {
                        int pos = atomicAdd(&g_edgeCount, 1);
                        if (pos < EDGE_MAX) g_edges[pos] = ((unsigned)i << 16) | (unsigned)j;
                    }
                }
            }
        }
    }

    // ========== last-finishing block: finalize ==========
    __shared__ int s_last2;
    __syncthreads();
    if (t == 0) {
        __threadfence();
        unsigned d = atomicAdd(&g_done2, 1u);
        s_last2 = (d == gridDim.x - 1) ? 1 : 0;
    }
    __syncthreads();
    if (!s_last2) return;

    for (int m = t; m < MM; m += 1024) sh.fin.dead[m] = (m < nV && g_keep0[m]) ? 0 : 1;
    int ec = g_edgeCount; if (ec > EDGE_MAX) ec = EDGE_MAX;
    for (int i = t; i < ec; i += 1024) sh.fin.se[i] = g_edges[i];
    __syncthreads();

    // parallel counting-rank sort of edges (distinct (i<<16|j) keys)
    for (int e = t; e < ec; e += 1024) {
        unsigned key = sh.fin.se[e];
        int r = 0;
        for (int f = 0; f < ec; f++) r += (sh.fin.se[f] < key) ? 1 : 0;
        sh.fin.se2[r] = key;
    }
    __syncthreads();

    if (t == 0) {
        for (int e = 0; e < ec; e++) {
            unsigned u = sh.fin.se2[e];
            int i = (int)(u >> 16), j = (int)(u & 0xFFFFu);
            if (!sh.fin.dead[i]) sh.fin.dead[j] = 1;
        }
    }
    __syncthreads();

    for (int m = t; m < MM; m += 1024) {
        bool keep = (sh.fin.dead[m] == 0);
        float4 b = g_boxes[m];
        out[m * 4 + 0] = keep ? b.x : 0.f;
        out[m * 4 + 1] = keep ? b.y : 0.f;
        out[m * 4 + 2] = keep ? b.z : 0.f;
        out[m * 4 + 3] = keep ? b.w : 0.f;
        out[MM * 4 + m] = keep ? 1.f : 0.f;
    }
    __syncthreads();
    if (t == 0) {   // reset for next replay
        g_candCount = 0;
        g_edgeCount = 0;
        g_done2 = 0;
    }
}

// ---------------- launch ----------------
extern "C" void kernel_launch(void* const* d_in, const int* in_sizes, int n_in,
                              void* d_out, int out_size) {
    int si = 0;
    for (int i = 1; i < n_in; i++) if (in_sizes[i] < in_sizes[si]) si = i;
    int others[2], o = 0;
    for (int i = 0; i < n_in && o < 2; i++) if (i != si) others[o++] = i;

    const float4* anchors = (const float4*)d_in[others[0]];
    const float2* score   = (const float2*)d_in[si];
    const float4* deltas  = (const float4*)d_in[others[1]];
    int n  = in_sizes[si] / 2;
    int n4 = in_sizes[si] / 4;

    k_all2<<<GRID, 1024>>>((const float4*)score, n4, score, n,
                           anchors, deltas, (float*)d_out);
}